// round 1
// baseline (speedup 1.0000x reference)
#include <cuda_runtime.h>

// LIF update: elementwise over N = 64*256*32*32 = 16,777,216 f32 elements.
// Inputs (metadata order): impulse, mem, refrac_until, spiketrain (unused values).
// Output: 4*N floats: [psp | mem_out | refrac_out | spiketrain_out].
//
// Constants baked from the reference config:
//   TIME=5.0, TAU_REFRAC=2.0 -> refrac reset = 7.0
//   V_THRESH=1.0, LEAK: subtract 0.1*DT (DT=1.0) where mem>0.

__global__ void __launch_bounds__(256) spike_layer_kernel(
    const float4* __restrict__ impulse,
    const float4* __restrict__ mem,
    const float4* __restrict__ refrac_until,
    float4* __restrict__ out_psp,
    float4* __restrict__ out_mem,
    float4* __restrict__ out_refrac,
    float4* __restrict__ out_spiketrain,
    int n4)
{
    int i = blockIdx.x * blockDim.x + threadIdx.x;
    if (i >= n4) return;

    const float TIME = 5.0f;
    const float REFRAC_RESET = 7.0f;   // TIME + TAU_REFRAC
    const float V_THRESH = 1.0f;
    const float LEAK_AMT = 0.1f;       // 0.1 * DT

    float4 imp = impulse[i];
    float4 m   = mem[i];
    float4 ru  = refrac_until[i];

    float4 psp, mo, ro, so;

    {
        float mi = (ru.x > TIME) ? 0.0f : imp.x;
        float nm = m.x + mi;
        nm = (nm > 0.0f) ? nm - LEAK_AMT : nm;
        bool sp = (nm >= V_THRESH);
        psp.x = sp ? V_THRESH : 0.0f;
        mo.x  = sp ? 0.0f : nm;
        ro.x  = sp ? REFRAC_RESET : ru.x;
        so.x  = sp ? TIME : 0.0f;
    }
    {
        float mi = (ru.y > TIME) ? 0.0f : imp.y;
        float nm = m.y + mi;
        nm = (nm > 0.0f) ? nm - LEAK_AMT : nm;
        bool sp = (nm >= V_THRESH);
        psp.y = sp ? V_THRESH : 0.0f;
        mo.y  = sp ? 0.0f : nm;
        ro.y  = sp ? REFRAC_RESET : ru.y;
        so.y  = sp ? TIME : 0.0f;
    }
    {
        float mi = (ru.z > TIME) ? 0.0f : imp.z;
        float nm = m.z + mi;
        nm = (nm > 0.0f) ? nm - LEAK_AMT : nm;
        bool sp = (nm >= V_THRESH);
        psp.z = sp ? V_THRESH : 0.0f;
        mo.z  = sp ? 0.0f : nm;
        ro.z  = sp ? REFRAC_RESET : ru.z;
        so.z  = sp ? TIME : 0.0f;
    }
    {
        float mi = (ru.w > TIME) ? 0.0f : imp.w;
        float nm = m.w + mi;
        nm = (nm > 0.0f) ? nm - LEAK_AMT : nm;
        bool sp = (nm >= V_THRESH);
        psp.w = sp ? V_THRESH : 0.0f;
        mo.w  = sp ? 0.0f : nm;
        ro.w  = sp ? REFRAC_RESET : ru.w;
        so.w  = sp ? TIME : 0.0f;
    }

    out_psp[i]        = psp;
    out_mem[i]        = mo;
    out_refrac[i]     = ro;
    out_spiketrain[i] = so;
}

extern "C" void kernel_launch(void* const* d_in, const int* in_sizes, int n_in,
                              void* d_out, int out_size)
{
    const float* impulse      = (const float*)d_in[0];
    const float* mem          = (const float*)d_in[1];
    const float* refrac_until = (const float*)d_in[2];
    // d_in[3] (spiketrain) values are unused by the reference math.

    int n = in_sizes[0];          // 16,777,216
    int n4 = n / 4;               // divisible: shape product is a power of 2

    float* out = (float*)d_out;   // [psp | mem | refrac | spiketrain], each n floats

    int threads = 256;
    int blocks = (n4 + threads - 1) / threads;

    spike_layer_kernel<<<blocks, threads>>>(
        (const float4*)impulse,
        (const float4*)mem,
        (const float4*)refrac_until,
        (float4*)(out),
        (float4*)(out + (size_t)n),
        (float4*)(out + (size_t)2 * n),
        (float4*)(out + (size_t)3 * n),
        n4);
}